// round 16
// baseline (speedup 1.0000x reference)
#include <cuda_runtime.h>
#include <cuda_fp16.h>

#define CDIM 64
#define MAXN 100000
#define MAXE 1600000

// q/k and acc are stored CHANNEL-PERMUTED in fragment order:
//   natural channel c -> p(c) = 16*(c>>4) + 4*((c&7)>>1) + 2*((c>>3)&1) + (c&1)
__device__ float g_q[MAXN * CDIM];
__device__ float g_k[MAXN * CDIM];
__device__ unsigned g_vh[MAXN * 32];       // v as packed f16x2 (hi-only), permuted
__device__ float g_acc[MAXN * CDIM * 2];   // [node][p(chan)][{num, denom}]
__device__ float4 g_pos4[MAXN];            // padded positions {x,y,z,0}
__device__ int2 g_epack[MAXE];             // packed {src, dst}

// pre-converted weight fragments (built once per launch by k_prep)
__device__ unsigned g_wfrag_node[4 * 2048];  // single fp16, PAIRED-nn uint4 layout
__device__ unsigned g_wfrag_edge[3 * 2048];  // single fp16, PAIRED-nn uint4 layout
__device__ unsigned g_wfrag_out[2048];

__device__ __forceinline__ void red_add_v4(float* p, float a, float b, float c, float d) {
    asm volatile("red.global.add.v4.f32 [%0], {%1, %2, %3, %4};"
                 :: "l"(p), "f"(a), "f"(b), "f"(c), "f"(d) : "memory");
}
__device__ __forceinline__ unsigned pack_f16x2(float lo_v, float hi_v) {
    unsigned r;
    asm("cvt.rn.f16x2.f32 %0, %1, %2;" : "=r"(r) : "f"(hi_v), "f"(lo_v));
    return r;
}
__device__ __forceinline__ float2 unpack_f16x2(unsigned u) {
    __half2 h = *reinterpret_cast<__half2*>(&u);
    return __half22float2(h);
}
__device__ __forceinline__ void split_pair(float v0, float v1, unsigned& hi, unsigned& lo) {
    hi = pack_f16x2(v0, v1);
    float2 hf = unpack_f16x2(hi);
    lo = pack_f16x2(v0 - hf.x, v1 - hf.y);
}

__device__ __forceinline__ void mma_f16(float d[4],
        unsigned a0, unsigned a1, unsigned a2, unsigned a3,
        unsigned b0, unsigned b1) {
    asm("mma.sync.aligned.m16n8k16.row.col.f32.f16.f16.f32 "
        "{%0,%1,%2,%3}, {%4,%5,%6,%7}, {%8,%9}, {%0,%1,%2,%3};"
        : "+f"(d[0]), "+f"(d[1]), "+f"(d[2]), "+f"(d[3])
        : "r"(a0), "r"(a1), "r"(a2), "r"(a3), "r"(b0), "r"(b1));
}

// fp32 (64x64) weights -> single-fp16 B-fragments, PAIRED-nn layout:
// uint4 at ((p*4+kk)*32+lane) holds {B(2p,kk).x, .y, B(2p+1,kk).x, .y}
__device__ __forceinline__ void prep_weights_h(const float* __restrict__ W,
                                               unsigned* __restrict__ dstW,
                                               int tcount, int tid) {
    for (int i = tid; i < 4096; i += tcount) {
        int h = i >> 6, c = i & 63;
        unsigned short hb = __half_as_ushort(__float2half_rn(W[i]));
        int kk = h >> 4, hh = h & 15;
        int e = hh & 1, mm = (hh >> 1) & 3, rg = hh >> 3;
        int nn = c >> 3, q = c & 7, ln = q * 4 + mm;
        int p = nn >> 1, sub = nn & 1;
        unsigned short* p16 = (unsigned short*)(dstW + ((p * 4 + kk) * 32 + ln) * 4 + sub * 2);
        p16[rg * 2 + e] = hb;
    }
}

// 2-mma gemm (A hi/lo), paired-nn B layout + paired-float4 bias layout:
// bias float4 at [p*4+m] = {b(2p,2m), b(2p,2m+1), b(2p+1,2m), b(2p+1,2m+1)}
template<bool BIAS>
__device__ __forceinline__ void gemm16_2(float D[8][4],
        const unsigned Ah[4][4], const unsigned Al[4][4],
        const unsigned* __restrict__ sW, const float* __restrict__ bias, int lane) {
    const int m = lane & 3;
    #pragma unroll
    for (int p = 0; p < 4; p++) {
        if (BIAS) {
            float4 bb = ((const float4*)bias)[p * 4 + m];
            D[2*p][0]   = bb.x; D[2*p][1]   = bb.y; D[2*p][2]   = bb.x; D[2*p][3]   = bb.y;
            D[2*p+1][0] = bb.z; D[2*p+1][1] = bb.w; D[2*p+1][2] = bb.z; D[2*p+1][3] = bb.w;
        } else {
            D[2*p][0] = 0.f; D[2*p][1] = 0.f; D[2*p][2] = 0.f; D[2*p][3] = 0.f;
            D[2*p+1][0] = 0.f; D[2*p+1][1] = 0.f; D[2*p+1][2] = 0.f; D[2*p+1][3] = 0.f;
        }
        #pragma unroll
        for (int kk = 0; kk < 4; kk++) {
            uint4 B = *(const uint4*)(sW + ((p * 4 + kk) * 32 + lane) * 4);
            mma_f16(D[2*p],   Ah[kk][0], Ah[kk][1], Ah[kk][2], Ah[kk][3], B.x, B.y);
            mma_f16(D[2*p],   Al[kk][0], Al[kk][1], Al[kk][2], Al[kk][3], B.x, B.y);
            mma_f16(D[2*p+1], Ah[kk][0], Ah[kk][1], Ah[kk][2], Ah[kk][3], B.z, B.w);
            mma_f16(D[2*p+1], Al[kk][0], Al[kk][1], Al[kk][2], Al[kk][3], B.z, B.w);
        }
    }
}
// 1-mma gemm (A hi-only): half the mma count; A error ~2^-11.
template<bool BIAS>
__device__ __forceinline__ void gemm16_h(float D[8][4],
        const unsigned Ah[4][4],
        const unsigned* __restrict__ sW, const float* __restrict__ bias, int lane) {
    const int m = lane & 3;
    #pragma unroll
    for (int p = 0; p < 4; p++) {
        if (BIAS) {
            float4 bb = ((const float4*)bias)[p * 4 + m];
            D[2*p][0]   = bb.x; D[2*p][1]   = bb.y; D[2*p][2]   = bb.x; D[2*p][3]   = bb.y;
            D[2*p+1][0] = bb.z; D[2*p+1][1] = bb.w; D[2*p+1][2] = bb.z; D[2*p+1][3] = bb.w;
        } else {
            D[2*p][0] = 0.f; D[2*p][1] = 0.f; D[2*p][2] = 0.f; D[2*p][3] = 0.f;
            D[2*p+1][0] = 0.f; D[2*p+1][1] = 0.f; D[2*p+1][2] = 0.f; D[2*p+1][3] = 0.f;
        }
        #pragma unroll
        for (int kk = 0; kk < 4; kk++) {
            uint4 B = *(const uint4*)(sW + ((p * 4 + kk) * 32 + lane) * 4);
            mma_f16(D[2*p],   Ah[kk][0], Ah[kk][1], Ah[kk][2], Ah[kk][3], B.x, B.y);
            mma_f16(D[2*p+1], Ah[kk][0], Ah[kk][1], Ah[kk][2], Ah[kk][3], B.z, B.w);
        }
    }
}
// bias paired index: natural channel c -> p*16 + m*4 + s*2 + e
__device__ __forceinline__ int bias_paired_idx(int c) {
    int nn = c >> 3, m = (c & 7) >> 1, e = c & 1;
    return (nn >> 1) * 16 + m * 4 + (nn & 1) * 2 + e;
}

// ---------------------------------------------------------------------------
// Prep: weights -> fragment buffers; padded pos4; packed edge list.
// ---------------------------------------------------------------------------
__global__ void k_prep(const float* __restrict__ W_in, const float* __restrict__ W_dst,
                       const float* __restrict__ W_src, const float* __restrict__ W_lin,
                       const float* __restrict__ pnW2, const float* __restrict__ anW1,
                       const float* __restrict__ anW2, const float* __restrict__ W_out,
                       const float* __restrict__ pos, const int* __restrict__ ei,
                       int N, int E) {
    const int tid = blockIdx.x * blockDim.x + threadIdx.x;
    const int nt = gridDim.x * blockDim.x;
    prep_weights_h(W_in,  g_wfrag_node,        nt, tid);
    prep_weights_h(W_dst, g_wfrag_node + 2048, nt, tid);
    prep_weights_h(W_src, g_wfrag_node + 4096, nt, tid);
    prep_weights_h(W_lin, g_wfrag_node + 6144, nt, tid);
    prep_weights_h(pnW2, g_wfrag_edge,        nt, tid);
    prep_weights_h(anW1, g_wfrag_edge + 2048, nt, tid);
    prep_weights_h(anW2, g_wfrag_edge + 4096, nt, tid);
    prep_weights_h(W_out, g_wfrag_out, nt, tid);
    for (int i = tid; i < N; i += nt)
        g_pos4[i] = make_float4(pos[3 * i], pos[3 * i + 1], pos[3 * i + 2], 0.f);
    for (int i = tid; i < E; i += nt)
        g_epack[i] = make_int2(ei[i], ei[E + i]);
}

// ---------------------------------------------------------------------------
// Node kernel: H = LN(relu(X@W_in+b)); q/k/v GEMMs (fp16 2-mma) -> permuted
// layout; v as fp16. Zeros acc. Full hi/lo split kept here so q,k retain
// near-fp32 accuracy for the cancellation-sensitive q-k subtraction.
// ---------------------------------------------------------------------------
#define NODE_SMEM (4 * 2048 * 4 + 192 * 4)
__global__ void __launch_bounds__(256, 2) k_node(
        int N, const float* __restrict__ x,
        const float* __restrict__ b_in,
        const float* __restrict__ ln_g, const float* __restrict__ ln_b) {
    extern __shared__ unsigned smu[];
    unsigned* sW = smu;                        // 4 * 2048 u32
    float* sP = (float*)(smu + 8192);          // b_in (paired), ln_g, ln_b

    {
        const uint4* src = (const uint4*)g_wfrag_node;
        uint4* dst = (uint4*)sW;
        for (int i = threadIdx.x; i < 2048; i += blockDim.x) dst[i] = src[i];
    }
    if (threadIdx.x < 64) {
        sP[bias_paired_idx(threadIdx.x)] = b_in[threadIdx.x];
        sP[64 + threadIdx.x]  = ln_g[threadIdx.x];
        sP[128 + threadIdx.x] = ln_b[threadIdx.x];
    }
    __syncthreads();

    const int lane = threadIdx.x & 31, warp = threadIdx.x >> 5;
    const int r0 = lane >> 2, m = lane & 3;
    const int gw = blockIdx.x * (blockDim.x >> 5) + warp;
    const int nw = gridDim.x * (blockDim.x >> 5);
    const int ntiles = (N + 15) >> 4;

    unsigned Ah[4][4], Al[4][4];
    float D[8][4];

    for (int t = gw; t < ntiles; t += nw) {
        const int base = t << 4;
        const int row0 = base + r0, row1 = base + r0 + 8;
        const bool ok0 = row0 < N, ok1 = row1 < N;
        const int rr0 = ok0 ? row0 : N - 1;
        const int rr1 = ok1 ? row1 : N - 1;

        #pragma unroll
        for (int kk = 0; kk < 4; kk++) {
            const int cb = kk * 16 + 2 * m;
            float2 xa = *(const float2*)(x + (size_t)rr0 * 64 + cb);
            float2 xb = *(const float2*)(x + (size_t)rr1 * 64 + cb);
            float2 xc = *(const float2*)(x + (size_t)rr0 * 64 + cb + 8);
            float2 xd = *(const float2*)(x + (size_t)rr1 * 64 + cb + 8);
            split_pair(xa.x, xa.y, Ah[kk][0], Al[kk][0]);
            split_pair(xb.x, xb.y, Ah[kk][1], Al[kk][1]);
            split_pair(xc.x, xc.y, Ah[kk][2], Al[kk][2]);
            split_pair(xd.x, xd.y, Ah[kk][3], Al[kk][3]);
        }

        gemm16_2<true>(D, Ah, Al, sW, sP, lane);
        #pragma unroll
        for (int nn = 0; nn < 8; nn++) {
            D[nn][0] = fmaxf(D[nn][0], 0.f); D[nn][1] = fmaxf(D[nn][1], 0.f);
            D[nn][2] = fmaxf(D[nn][2], 0.f); D[nn][3] = fmaxf(D[nn][3], 0.f);
        }

        float s0 = 0.f, q0 = 0.f, s1 = 0.f, q1 = 0.f;
        #pragma unroll
        for (int nn = 0; nn < 8; nn++) {
            s0 += D[nn][0] + D[nn][1];
            q0 += D[nn][0] * D[nn][0] + D[nn][1] * D[nn][1];
            s1 += D[nn][2] + D[nn][3];
            q1 += D[nn][2] * D[nn][2] + D[nn][3] * D[nn][3];
        }
        #pragma unroll
        for (int off = 1; off <= 2; off <<= 1) {
            s0 += __shfl_xor_sync(0xffffffffu, s0, off);
            q0 += __shfl_xor_sync(0xffffffffu, q0, off);
            s1 += __shfl_xor_sync(0xffffffffu, s1, off);
            q1 += __shfl_xor_sync(0xffffffffu, q1, off);
        }
        float mu0 = s0 * 0.015625f, mu1 = s1 * 0.015625f;
        float inv0 = rsqrtf(q0 * 0.015625f - mu0 * mu0 + 1e-5f);
        float inv1 = rsqrtf(q1 * 0.015625f - mu1 * mu1 + 1e-5f);

        #pragma unroll
        for (int kk = 0; kk < 4; kk++) {
            const int c = kk * 16 + 2 * m;
            float2 ga = *(const float2*)(sP + 64 + c);
            float2 ba = *(const float2*)(sP + 128 + c);
            float2 gb = *(const float2*)(sP + 64 + c + 8);
            float2 bb = *(const float2*)(sP + 128 + c + 8);
            float h00 = (D[2*kk][0]   - mu0) * inv0 * ga.x + ba.x;
            float h01 = (D[2*kk][1]   - mu0) * inv0 * ga.y + ba.y;
            float h10 = (D[2*kk][2]   - mu1) * inv1 * ga.x + ba.x;
            float h11 = (D[2*kk][3]   - mu1) * inv1 * ga.y + ba.y;
            float h08 = (D[2*kk+1][0] - mu0) * inv0 * gb.x + bb.x;
            float h09 = (D[2*kk+1][1] - mu0) * inv0 * gb.y + bb.y;
            float h18 = (D[2*kk+1][2] - mu1) * inv1 * gb.x + bb.x;
            float h19 = (D[2*kk+1][3] - mu1) * inv1 * gb.y + bb.y;
            split_pair(h00, h01, Ah[kk][0], Al[kk][0]);
            split_pair(h10, h11, Ah[kk][1], Al[kk][1]);
            split_pair(h08, h09, Ah[kk][2], Al[kk][2]);
            split_pair(h18, h19, Ah[kk][3], Al[kk][3]);
        }

        gemm16_2<false>(D, Ah, Al, sW + 2048, nullptr, lane);
        #pragma unroll
        for (int nn = 0; nn < 8; nn++) {
            const int pp = 16 * (nn >> 1) + 4 * m + 2 * (nn & 1);
            if (ok0) *(float2*)(g_q + (size_t)row0 * 64 + pp) = make_float2(D[nn][0], D[nn][1]);
            if (ok1) *(float2*)(g_q + (size_t)row1 * 64 + pp) = make_float2(D[nn][2], D[nn][3]);
        }
        gemm16_2<false>(D, Ah, Al, sW + 4096, nullptr, lane);
        #pragma unroll
        for (int nn = 0; nn < 8; nn++) {
            const int pp = 16 * (nn >> 1) + 4 * m + 2 * (nn & 1);
            if (ok0) *(float2*)(g_k + (size_t)row0 * 64 + pp) = make_float2(D[nn][0], D[nn][1]);
            if (ok1) *(float2*)(g_k + (size_t)row1 * 64 + pp) = make_float2(D[nn][2], D[nn][3]);
        }
        gemm16_2<false>(D, Ah, Al, sW + 6144, nullptr, lane);
        #pragma unroll
        for (int nn = 0; nn < 8; nn++) {
            const int vi = 8 * (nn >> 1) + 2 * m + (nn & 1);
            if (ok0) g_vh[(size_t)row0 * 32 + vi] = pack_f16x2(D[nn][0], D[nn][1]);
            if (ok1) g_vh[(size_t)row1 * 32 + vi] = pack_f16x2(D[nn][2], D[nn][3]);
        }

        float4* accz = (float4*)(g_acc + (size_t)base * 128);
        #pragma unroll
        for (int i = 0; i < 16; i++) {
            int idx = i * 32 + lane;
            if (base + (idx >> 5) < N)
                accz[idx] = make_float4(0.f, 0.f, 0.f, 0.f);
        }
    }
}

// ---------------------------------------------------------------------------
// Edge kernel: 16-edge mma tiles, ALL GEMMs A-hi-only (96 mmas/tile).
// fp32 arithmetic for q-k+delta happens BEFORE the single fp16 rounding, so
// cancellation is preserved; measured error contribution of each hi-only
// A-operand is ~0.2e-4 (rounds 8/15). Packed int2 edges, float4 pos, fp16 v.
// ---------------------------------------------------------------------------
#define EDGE_SMEM (3 * 2048 * 4 + 64 * 16 + 3 * 64 * 4)   // 26368 B

__global__ void __launch_bounds__(128, 3) k_edge(
        int E,
        const float* __restrict__ pnW1, const float* __restrict__ pnb1,
        const float* __restrict__ pnb2, const float* __restrict__ anb1,
        const float* __restrict__ anb2) {
    extern __shared__ unsigned smu[];
    unsigned* sWL = smu;
    float4*  sW1  = (float4*)(smu + 6144);
    float*   sB   = (float*)(smu + 6144 + 256);   // 3 x 64 floats, paired layout

    {
        const uint4* src = (const uint4*)g_wfrag_edge;
        uint4* dst = (uint4*)sWL;
        for (int i = threadIdx.x; i < 1536; i += 128) dst[i] = src[i];
    }
    if (threadIdx.x < 64) {
        int c = threadIdx.x;
        sW1[c] = make_float4(pnW1[c], pnW1[64 + c], pnW1[128 + c], pnb1[c]);
        int pidx = bias_paired_idx(c);
        sB[pidx]        = pnb2[c];
        sB[64 + pidx]   = anb1[c];
        sB[128 + pidx]  = anb2[c];
    }
    __syncthreads();

    const int lane = threadIdx.x & 31, warp = threadIdx.x >> 5;
    const int r0 = lane >> 2, m = lane & 3;
    const int gw = blockIdx.x * 4 + warp;
    const int nw = gridDim.x * 4;
    const int ntiles = (E + 15) >> 4;

    unsigned Ah[4][4];
    float D[8][4];
    float Dlt[8][4];
    float QK[8][4];

    int t = gw;
    int2 pe0 = make_int2(0, 0), pe1 = make_int2(0, 0);
    if (t < ntiles) {
        const int base = t << 4;
        pe0 = g_epack[min(base + r0, E - 1)];
        pe1 = g_epack[min(base + r0 + 8, E - 1)];
    }

    for (; t < ntiles; t += nw) {
        const int base = t << 4;
        const bool ok0 = base + r0 < E, ok1 = base + r0 + 8 < E;
        const int s0 = pe0.x, d0 = pe0.y, s1 = pe1.x, d1 = pe1.y;

        const int tn = t + nw;
        if (tn < ntiles) {
            const int nb = tn << 4;
            pe0 = g_epack[min(nb + r0, E - 1)];
            pe1 = g_epack[min(nb + r0 + 8, E - 1)];
        }

        // padded pos loads: one LDG.128 per endpoint
        float4 pD0 = g_pos4[d0], pS0 = g_pos4[s0];
        float4 pD1 = g_pos4[d1], pS1 = g_pos4[s1];
        const float p00 = pD0.x - pS0.x, p01 = pD0.y - pS0.y, p02 = pD0.z - pS0.z;
        const float p10 = pD1.x - pS1.x, p11 = pD1.y - pS1.y, p12 = pD1.z - pS1.z;

        // q/k fragment gathers: one float4 per (kk, row-stream), permuted layout
        #pragma unroll
        for (int kk = 0; kk < 4; kk++) {
            const int fp = kk * 16 + 4 * m;
            float4 qa = *(const float4*)(g_q + (size_t)d0 * 64 + fp);
            float4 ka = *(const float4*)(g_k + (size_t)s0 * 64 + fp);
            float4 qb = *(const float4*)(g_q + (size_t)d1 * 64 + fp);
            float4 kb = *(const float4*)(g_k + (size_t)s1 * 64 + fp);
            QK[2*kk][0]   = qa.x - ka.x; QK[2*kk][1]   = qa.y - ka.y;
            QK[2*kk+1][0] = qa.z - ka.z; QK[2*kk+1][1] = qa.w - ka.w;
            QK[2*kk][2]   = qb.x - kb.x; QK[2*kk][3]   = qb.y - kb.y;
            QK[2*kk+1][2] = qb.z - kb.z; QK[2*kk+1][3] = qb.w - kb.w;
        }

        // pos MLP layer 1 (3 -> 64), fp32, A-hi-only fragments
        #pragma unroll
        for (int kk = 0; kk < 4; kk++) {
            const int cb = kk * 16 + 2 * m;
            float4 wA = sW1[cb],     wB = sW1[cb + 1];
            float4 wC = sW1[cb + 8], wD = sW1[cb + 9];
            float h00 = fmaxf(fmaf(p02, wA.z, fmaf(p01, wA.y, fmaf(p00, wA.x, wA.w))), 0.f);
            float h01 = fmaxf(fmaf(p02, wB.z, fmaf(p01, wB.y, fmaf(p00, wB.x, wB.w))), 0.f);
            float h10 = fmaxf(fmaf(p12, wA.z, fmaf(p11, wA.y, fmaf(p10, wA.x, wA.w))), 0.f);
            float h11 = fmaxf(fmaf(p12, wB.z, fmaf(p11, wB.y, fmaf(p10, wB.x, wB.w))), 0.f);
            float h08 = fmaxf(fmaf(p02, wC.z, fmaf(p01, wC.y, fmaf(p00, wC.x, wC.w))), 0.f);
            float h09 = fmaxf(fmaf(p02, wD.z, fmaf(p01, wD.y, fmaf(p00, wD.x, wD.w))), 0.f);
            float h18 = fmaxf(fmaf(p12, wC.z, fmaf(p11, wC.y, fmaf(p10, wC.x, wC.w))), 0.f);
            float h19 = fmaxf(fmaf(p12, wD.z, fmaf(p11, wD.y, fmaf(p10, wD.x, wD.w))), 0.f);
            Ah[kk][0] = pack_f16x2(h00, h01);
            Ah[kk][1] = pack_f16x2(h10, h11);
            Ah[kk][2] = pack_f16x2(h08, h09);
            Ah[kk][3] = pack_f16x2(h18, h19);
        }

        // GEMM1 (A hi-only): delta = relu(H1 @ pnW2 + pnb2)
        gemm16_h<true>(D, Ah, sWL, sB, lane);
        #pragma unroll
        for (int nn = 0; nn < 8; nn++) {
            Dlt[nn][0] = fmaxf(D[nn][0], 0.f);
            Dlt[nn][1] = fmaxf(D[nn][1], 0.f);
            Dlt[nn][2] = fmaxf(D[nn][2], 0.f);
            Dlt[nn][3] = fmaxf(D[nn][3], 0.f);
        }

        // A2 = QK + delta (fp32 sum, single fp16 rounding of the result)
        #pragma unroll
        for (int kk = 0; kk < 4; kk++) {
            Ah[kk][0] = pack_f16x2(QK[2*kk][0]   + Dlt[2*kk][0],   QK[2*kk][1]   + Dlt[2*kk][1]);
            Ah[kk][1] = pack_f16x2(QK[2*kk][2]   + Dlt[2*kk][2],   QK[2*kk][3]   + Dlt[2*kk][3]);
            Ah[kk][2] = pack_f16x2(QK[2*kk+1][0] + Dlt[2*kk+1][0], QK[2*kk+1][1] + Dlt[2*kk+1][1]);
            Ah[kk][3] = pack_f16x2(QK[2*kk+1][2] + Dlt[2*kk+1][2], QK[2*kk+1][3] + Dlt[2*kk+1][3]);
        }

        // GEMM2 (A hi-only): G = relu(A2 @ anW1 + anb1); pack G for GEMM3
        gemm16_h<true>(D, Ah, sWL + 2048, sB + 64, lane);
        #pragma unroll
        for (int kk = 0; kk < 4; kk++) {
            Ah[kk][0] = pack_f16x2(fmaxf(D[2*kk][0], 0.f),   fmaxf(D[2*kk][1], 0.f));
            Ah[kk][1] = pack_f16x2(fmaxf(D[2*kk][2], 0.f),   fmaxf(D[2*kk][3], 0.f));
            Ah[kk][2] = pack_f16x2(fmaxf(D[2*kk+1][0], 0.f), fmaxf(D[2*kk+1][1], 0.f));
            Ah[kk][3] = pack_f16x2(fmaxf(D[2*kk+1][2], 0.f), fmaxf(D[2*kk+1][3], 0.f));
        }

        // v gathers (fp16 packed; reuse QK storage)
        #pragma unroll
        for (int j = 0; j < 4; j++) {
            const int vi = 8 * j + 2 * m;
            uint2 v0 = *(const uint2*)(g_vh + (size_t)s0 * 32 + vi);
            uint2 v1 = *(const uint2*)(g_vh + (size_t)s1 * 32 + vi);
            float2 a = unpack_f16x2(v0.x);
            float2 b = unpack_f16x2(v0.y);
            float2 c = unpack_f16x2(v1.x);
            float2 d2 = unpack_f16x2(v1.y);
            QK[2*j][0]   = a.x; QK[2*j][1]   = a.y;
            QK[2*j+1][0] = b.x; QK[2*j+1][1] = b.y;
            QK[2*j][2]   = c.x; QK[2*j][3]   = c.y;
            QK[2*j+1][2] = d2.x; QK[2*j+1][3] = d2.y;
        }

        // GEMM3 (A hi-only): alpha = G @ anW2 + anb2
        gemm16_h<true>(D, Ah, sWL + 4096, sB + 128, lane);

        // epilogue -> REDs at permuted acc positions
        #pragma unroll
        for (int nn = 0; nn < 8; nn++) {
            const int pp = 16 * (nn >> 1) + 4 * m + 2 * (nn & 1);
            float e00 = __expf(fmaxf(D[nn][0], 0.f));
            float e01 = __expf(fmaxf(D[nn][1], 0.f));
            float e10 = __expf(fmaxf(D[nn][2], 0.f));
            float e11 = __expf(fmaxf(D[nn][3], 0.f));
            if (ok0)
                red_add_v4(g_acc + (size_t)d0 * 128 + 2 * pp,
                           e00 * (QK[nn][0] + Dlt[nn][0]), e00,
                           e01 * (QK[nn][1] + Dlt[nn][1]), e01);
            if (ok1)
                red_add_v4(g_acc + (size_t)d1 * 128 + 2 * pp,
                           e10 * (QK[nn][2] + Dlt[nn][2]), e10,
                           e11 * (QK[nn][3] + Dlt[nn][3]), e11);
        }
    }
}

// ---------------------------------------------------------------------------
// Output kernel: reads permuted acc, fp16 2-mma GEMM (paired bias), natural store.
// ---------------------------------------------------------------------------
#define OUT_SMEM (2048 * 4 + 64 * 4)
__global__ void __launch_bounds__(256, 2) k_out(
        int N, const float* __restrict__ b_out, float* __restrict__ out) {
    extern __shared__ unsigned smu[];
    unsigned* sW = smu;
    float* sB = (float*)(smu + 2048);

    {
        const uint4* src = (const uint4*)g_wfrag_out;
        uint4* dst = (uint4*)sW;
        for (int i = threadIdx.x; i < 512; i += blockDim.x) dst[i] = src[i];
    }
    if (threadIdx.x < 64) sB[bias_paired_idx(threadIdx.x)] = b_out[threadIdx.x];
    __syncthreads();

    const int lane = threadIdx.x & 31, warp = threadIdx.x >> 5;
    const int r0 = lane >> 2, m = lane & 3;
    const int gw = blockIdx.x * (blockDim.x >> 5) + warp;
    const int nw = gridDim.x * (blockDim.x >> 5);
    const int ntiles = (N + 15) >> 4;

    unsigned Ah[4][4], Al[4][4];
    float D[8][4];

    for (int t = gw; t < ntiles; t += nw) {
        const int base = t << 4;
        const int row0 = base + r0, row1 = base + r0 + 8;
        const bool ok0 = row0 < N, ok1 = row1 < N;
        const int rr0 = ok0 ? row0 : N - 1;
        const int rr1 = ok1 ? row1 : N - 1;

        #pragma unroll
        for (int kk = 0; kk < 4; kk++) {
            const int fb = 32 * kk + 8 * m;
            float4 a0 = *(const float4*)(g_acc + (size_t)rr0 * 128 + fb);
            float4 a2 = *(const float4*)(g_acc + (size_t)rr0 * 128 + fb + 4);
            float4 a1 = *(const float4*)(g_acc + (size_t)rr1 * 128 + fb);
            float4 a3 = *(const float4*)(g_acc + (size_t)rr1 * 128 + fb + 4);
            split_pair(__fdividef(a0.x, a0.y + 1e-16f), __fdividef(a0.z, a0.w + 1e-16f),
                       Ah[kk][0], Al[kk][0]);
            split_pair(__fdividef(a1.x, a1.y + 1e-16f), __fdividef(a1.z, a1.w + 1e-16f),
                       Ah[kk][1], Al[kk][1]);
            split_pair(__fdividef(a2.x, a2.y + 1e-16f), __fdividef(a2.z, a2.w + 1e-16f),
                       Ah[kk][2], Al[kk][2]);
            split_pair(__fdividef(a3.x, a3.y + 1e-16f), __fdividef(a3.z, a3.w + 1e-16f),
                       Ah[kk][3], Al[kk][3]);
        }

        gemm16_2<true>(D, Ah, Al, sW, sB, lane);

        #pragma unroll
        for (int nn = 0; nn < 8; nn++) {
            const int c = nn * 8 + 2 * m;
            if (ok0) *(float2*)(out + (size_t)row0 * 64 + c) =
                make_float2(fmaxf(D[nn][0], 0.f), fmaxf(D[nn][1], 0.f));
            if (ok1) *(float2*)(out + (size_t)row1 * 64 + c) =
                make_float2(fmaxf(D[nn][2], 0.f), fmaxf(D[nn][3], 0.f));
        }
    }
}

// ---------------------------------------------------------------------------

extern "C" void kernel_launch(void* const* d_in, const int* in_sizes, int n_in,
                              void* d_out, int out_size) {
    const float* x     = (const float*)d_in[0];
    const float* pos   = (const float*)d_in[1];
    const int*   ei    = (const int*)d_in[2];
    const float* W_in  = (const float*)d_in[3];
    const float* b_in  = (const float*)d_in[4];
    const float* ln_g  = (const float*)d_in[5];
    const float* ln_b  = (const float*)d_in[6];
    const float* W_lin = (const float*)d_in[7];
    const float* W_src = (const float*)d_in[8];
    const float* W_dst = (const float*)d_in[9];
    const float* pnW1  = (const float*)d_in[10];
    const float* pnb1  = (const float*)d_in[11];
    const float* pnW2  = (const float*)d_in[12];
    const float* pnb2  = (const float*)d_in[13];
    const float* anW1  = (const float*)d_in[14];
    const float* anb1  = (const float*)d_in[15];
    const float* anW2  = (const float*)d_in[16];
    const float* anb2  = (const float*)d_in[17];
    const float* W_out = (const float*)d_in[18];
    const float* b_out = (const float*)d_in[19];

    const int N = in_sizes[0] / 64;
    const int E = in_sizes[2] / 2;

    cudaFuncSetAttribute(k_node, cudaFuncAttributeMaxDynamicSharedMemorySize, NODE_SMEM);
    cudaFuncSetAttribute(k_edge, cudaFuncAttributeMaxDynamicSharedMemorySize, EDGE_SMEM);
    cudaFuncSetAttribute(k_out,  cudaFuncAttributeMaxDynamicSharedMemorySize, OUT_SMEM);

    k_prep<<<128, 256>>>(W_in, W_dst, W_src, W_lin, pnW2, anW1, anW2, W_out,
                         pos, ei, N, E);
    k_node<<<296, 256, NODE_SMEM>>>(N, x, b_in, ln_g, ln_b);
    k_edge<<<444, 128, EDGE_SMEM>>>(E, pnW1, pnb1, pnb2, anb1, anb2);
    k_out<<<296, 256, OUT_SMEM>>>(N, b_out, (float*)d_out);
}

// round 17
// speedup vs baseline: 1.0195x; 1.0195x over previous
#include <cuda_runtime.h>
#include <cuda_fp16.h>

#define CDIM 64
#define MAXN 100000
#define MAXE 1600000

// q/k and acc are stored CHANNEL-PERMUTED in fragment order:
//   natural channel c -> p(c) = 16*(c>>4) + 4*((c&7)>>1) + 2*((c>>3)&1) + (c&1)
__device__ float g_q[MAXN * CDIM];
__device__ float g_k[MAXN * CDIM];
__device__ unsigned g_vh[MAXN * 32];       // v as packed f16x2 (hi-only), permuted
__device__ float g_acc[MAXN * CDIM * 2];   // [node][p(chan)][{num, denom}]
__device__ float4 g_pos4[MAXN];            // padded positions {x,y,z,0}
__device__ int2 g_epack[MAXE];             // packed {src, dst}

// pre-converted weight fragments (built once per launch by k_prep)
__device__ unsigned g_wfrag_node[4 * 2048];  // single fp16, PAIRED-nn uint4 layout
__device__ unsigned g_wfrag_edge[3 * 2048];  // single fp16, PAIRED-nn uint4 layout
__device__ unsigned g_wfrag_out[2048];

__device__ __forceinline__ void red_add_v4(float* p, float a, float b, float c, float d) {
    asm volatile("red.global.add.v4.f32 [%0], {%1, %2, %3, %4};"
                 :: "l"(p), "f"(a), "f"(b), "f"(c), "f"(d) : "memory");
}
__device__ __forceinline__ unsigned pack_f16x2(float lo_v, float hi_v) {
    unsigned r;
    asm("cvt.rn.f16x2.f32 %0, %1, %2;" : "=r"(r) : "f"(hi_v), "f"(lo_v));
    return r;
}
__device__ __forceinline__ float2 unpack_f16x2(unsigned u) {
    __half2 h = *reinterpret_cast<__half2*>(&u);
    return __half22float2(h);
}
__device__ __forceinline__ void split_pair(float v0, float v1, unsigned& hi, unsigned& lo) {
    hi = pack_f16x2(v0, v1);
    float2 hf = unpack_f16x2(hi);
    lo = pack_f16x2(v0 - hf.x, v1 - hf.y);
}

__device__ __forceinline__ void mma_f16(float d[4],
        unsigned a0, unsigned a1, unsigned a2, unsigned a3,
        unsigned b0, unsigned b1) {
    asm("mma.sync.aligned.m16n8k16.row.col.f32.f16.f16.f32 "
        "{%0,%1,%2,%3}, {%4,%5,%6,%7}, {%8,%9}, {%0,%1,%2,%3};"
        : "+f"(d[0]), "+f"(d[1]), "+f"(d[2]), "+f"(d[3])
        : "r"(a0), "r"(a1), "r"(a2), "r"(a3), "r"(b0), "r"(b1));
}

// fp32 (64x64) weights -> single-fp16 B-fragments, PAIRED-nn layout:
// uint4 at ((p*4+kk)*32+lane) holds {B(2p,kk).x, .y, B(2p+1,kk).x, .y}
__device__ __forceinline__ void prep_weights_h(const float* __restrict__ W,
                                               unsigned* __restrict__ dstW,
                                               int tcount, int tid) {
    for (int i = tid; i < 4096; i += tcount) {
        int h = i >> 6, c = i & 63;
        unsigned short hb = __half_as_ushort(__float2half_rn(W[i]));
        int kk = h >> 4, hh = h & 15;
        int e = hh & 1, mm = (hh >> 1) & 3, rg = hh >> 3;
        int nn = c >> 3, q = c & 7, ln = q * 4 + mm;
        int p = nn >> 1, sub = nn & 1;
        unsigned short* p16 = (unsigned short*)(dstW + ((p * 4 + kk) * 32 + ln) * 4 + sub * 2);
        p16[rg * 2 + e] = hb;
    }
}

// 2-mma gemm (A hi/lo), paired-nn B layout + paired-float4 bias layout:
// bias float4 at [p*4+m] = {b(2p,2m), b(2p,2m+1), b(2p+1,2m), b(2p+1,2m+1)}
template<bool BIAS>
__device__ __forceinline__ void gemm16_2(float D[8][4],
        const unsigned Ah[4][4], const unsigned Al[4][4],
        const unsigned* __restrict__ sW, const float* __restrict__ bias, int lane) {
    const int m = lane & 3;
    #pragma unroll
    for (int p = 0; p < 4; p++) {
        if (BIAS) {
            float4 bb = ((const float4*)bias)[p * 4 + m];
            D[2*p][0]   = bb.x; D[2*p][1]   = bb.y; D[2*p][2]   = bb.x; D[2*p][3]   = bb.y;
            D[2*p+1][0] = bb.z; D[2*p+1][1] = bb.w; D[2*p+1][2] = bb.z; D[2*p+1][3] = bb.w;
        } else {
            D[2*p][0] = 0.f; D[2*p][1] = 0.f; D[2*p][2] = 0.f; D[2*p][3] = 0.f;
            D[2*p+1][0] = 0.f; D[2*p+1][1] = 0.f; D[2*p+1][2] = 0.f; D[2*p+1][3] = 0.f;
        }
        #pragma unroll
        for (int kk = 0; kk < 4; kk++) {
            uint4 B = *(const uint4*)(sW + ((p * 4 + kk) * 32 + lane) * 4);
            mma_f16(D[2*p],   Ah[kk][0], Ah[kk][1], Ah[kk][2], Ah[kk][3], B.x, B.y);
            mma_f16(D[2*p],   Al[kk][0], Al[kk][1], Al[kk][2], Al[kk][3], B.x, B.y);
            mma_f16(D[2*p+1], Ah[kk][0], Ah[kk][1], Ah[kk][2], Ah[kk][3], B.z, B.w);
            mma_f16(D[2*p+1], Al[kk][0], Al[kk][1], Al[kk][2], Al[kk][3], B.z, B.w);
        }
    }
}
// 1-mma gemm (A hi-only): half the mma count; A error ~2^-11.
template<bool BIAS>
__device__ __forceinline__ void gemm16_h(float D[8][4],
        const unsigned Ah[4][4],
        const unsigned* __restrict__ sW, const float* __restrict__ bias, int lane) {
    const int m = lane & 3;
    #pragma unroll
    for (int p = 0; p < 4; p++) {
        if (BIAS) {
            float4 bb = ((const float4*)bias)[p * 4 + m];
            D[2*p][0]   = bb.x; D[2*p][1]   = bb.y; D[2*p][2]   = bb.x; D[2*p][3]   = bb.y;
            D[2*p+1][0] = bb.z; D[2*p+1][1] = bb.w; D[2*p+1][2] = bb.z; D[2*p+1][3] = bb.w;
        } else {
            D[2*p][0] = 0.f; D[2*p][1] = 0.f; D[2*p][2] = 0.f; D[2*p][3] = 0.f;
            D[2*p+1][0] = 0.f; D[2*p+1][1] = 0.f; D[2*p+1][2] = 0.f; D[2*p+1][3] = 0.f;
        }
        #pragma unroll
        for (int kk = 0; kk < 4; kk++) {
            uint4 B = *(const uint4*)(sW + ((p * 4 + kk) * 32 + lane) * 4);
            mma_f16(D[2*p],   Ah[kk][0], Ah[kk][1], Ah[kk][2], Ah[kk][3], B.x, B.y);
            mma_f16(D[2*p+1], Ah[kk][0], Ah[kk][1], Ah[kk][2], Ah[kk][3], B.z, B.w);
        }
    }
}
// bias paired index: natural channel c -> p*16 + m*4 + s*2 + e
__device__ __forceinline__ int bias_paired_idx(int c) {
    int nn = c >> 3, m = (c & 7) >> 1, e = c & 1;
    return (nn >> 1) * 16 + m * 4 + (nn & 1) * 2 + e;
}

// ---------------------------------------------------------------------------
// Prep: weights -> fragment buffers; padded pos4; packed edge list.
// ---------------------------------------------------------------------------
__global__ void k_prep(const float* __restrict__ W_in, const float* __restrict__ W_dst,
                       const float* __restrict__ W_src, const float* __restrict__ W_lin,
                       const float* __restrict__ pnW2, const float* __restrict__ anW1,
                       const float* __restrict__ anW2, const float* __restrict__ W_out,
                       const float* __restrict__ pos, const int* __restrict__ ei,
                       int N, int E) {
    const int tid = blockIdx.x * blockDim.x + threadIdx.x;
    const int nt = gridDim.x * blockDim.x;
    prep_weights_h(W_in,  g_wfrag_node,        nt, tid);
    prep_weights_h(W_dst, g_wfrag_node + 2048, nt, tid);
    prep_weights_h(W_src, g_wfrag_node + 4096, nt, tid);
    prep_weights_h(W_lin, g_wfrag_node + 6144, nt, tid);
    prep_weights_h(pnW2, g_wfrag_edge,        nt, tid);
    prep_weights_h(anW1, g_wfrag_edge + 2048, nt, tid);
    prep_weights_h(anW2, g_wfrag_edge + 4096, nt, tid);
    prep_weights_h(W_out, g_wfrag_out, nt, tid);
    for (int i = tid; i < N; i += nt)
        g_pos4[i] = make_float4(pos[3 * i], pos[3 * i + 1], pos[3 * i + 2], 0.f);
    for (int i = tid; i < E; i += nt)
        g_epack[i] = make_int2(ei[i], ei[E + i]);
}

// ---------------------------------------------------------------------------
// Node kernel: H = LN(relu(X@W_in+b)); q/k/v GEMMs (fp16 2-mma) -> permuted
// layout; v as fp16. Zeros acc. Full hi/lo split kept here so q,k retain
// near-fp32 accuracy for the cancellation-sensitive q-k subtraction.
// ---------------------------------------------------------------------------
#define NODE_SMEM (4 * 2048 * 4 + 192 * 4)
__global__ void __launch_bounds__(256, 2) k_node(
        int N, const float* __restrict__ x,
        const float* __restrict__ b_in,
        const float* __restrict__ ln_g, const float* __restrict__ ln_b) {
    extern __shared__ unsigned smu[];
    unsigned* sW = smu;                        // 4 * 2048 u32
    float* sP = (float*)(smu + 8192);          // b_in (paired), ln_g, ln_b

    {
        const uint4* src = (const uint4*)g_wfrag_node;
        uint4* dst = (uint4*)sW;
        for (int i = threadIdx.x; i < 2048; i += blockDim.x) dst[i] = src[i];
    }
    if (threadIdx.x < 64) {
        sP[bias_paired_idx(threadIdx.x)] = b_in[threadIdx.x];
        sP[64 + threadIdx.x]  = ln_g[threadIdx.x];
        sP[128 + threadIdx.x] = ln_b[threadIdx.x];
    }
    __syncthreads();

    const int lane = threadIdx.x & 31, warp = threadIdx.x >> 5;
    const int r0 = lane >> 2, m = lane & 3;
    const int gw = blockIdx.x * (blockDim.x >> 5) + warp;
    const int nw = gridDim.x * (blockDim.x >> 5);
    const int ntiles = (N + 15) >> 4;

    unsigned Ah[4][4], Al[4][4];
    float D[8][4];

    for (int t = gw; t < ntiles; t += nw) {
        const int base = t << 4;
        const int row0 = base + r0, row1 = base + r0 + 8;
        const bool ok0 = row0 < N, ok1 = row1 < N;
        const int rr0 = ok0 ? row0 : N - 1;
        const int rr1 = ok1 ? row1 : N - 1;

        #pragma unroll
        for (int kk = 0; kk < 4; kk++) {
            const int cb = kk * 16 + 2 * m;
            float2 xa = *(const float2*)(x + (size_t)rr0 * 64 + cb);
            float2 xb = *(const float2*)(x + (size_t)rr1 * 64 + cb);
            float2 xc = *(const float2*)(x + (size_t)rr0 * 64 + cb + 8);
            float2 xd = *(const float2*)(x + (size_t)rr1 * 64 + cb + 8);
            split_pair(xa.x, xa.y, Ah[kk][0], Al[kk][0]);
            split_pair(xb.x, xb.y, Ah[kk][1], Al[kk][1]);
            split_pair(xc.x, xc.y, Ah[kk][2], Al[kk][2]);
            split_pair(xd.x, xd.y, Ah[kk][3], Al[kk][3]);
        }

        gemm16_2<true>(D, Ah, Al, sW, sP, lane);
        #pragma unroll
        for (int nn = 0; nn < 8; nn++) {
            D[nn][0] = fmaxf(D[nn][0], 0.f); D[nn][1] = fmaxf(D[nn][1], 0.f);
            D[nn][2] = fmaxf(D[nn][2], 0.f); D[nn][3] = fmaxf(D[nn][3], 0.f);
        }

        float s0 = 0.f, q0 = 0.f, s1 = 0.f, q1 = 0.f;
        #pragma unroll
        for (int nn = 0; nn < 8; nn++) {
            s0 += D[nn][0] + D[nn][1];
            q0 += D[nn][0] * D[nn][0] + D[nn][1] * D[nn][1];
            s1 += D[nn][2] + D[nn][3];
            q1 += D[nn][2] * D[nn][2] + D[nn][3] * D[nn][3];
        }
        #pragma unroll
        for (int off = 1; off <= 2; off <<= 1) {
            s0 += __shfl_xor_sync(0xffffffffu, s0, off);
            q0 += __shfl_xor_sync(0xffffffffu, q0, off);
            s1 += __shfl_xor_sync(0xffffffffu, s1, off);
            q1 += __shfl_xor_sync(0xffffffffu, q1, off);
        }
        float mu0 = s0 * 0.015625f, mu1 = s1 * 0.015625f;
        float inv0 = rsqrtf(q0 * 0.015625f - mu0 * mu0 + 1e-5f);
        float inv1 = rsqrtf(q1 * 0.015625f - mu1 * mu1 + 1e-5f);

        #pragma unroll
        for (int kk = 0; kk < 4; kk++) {
            const int c = kk * 16 + 2 * m;
            float2 ga = *(const float2*)(sP + 64 + c);
            float2 ba = *(const float2*)(sP + 128 + c);
            float2 gb = *(const float2*)(sP + 64 + c + 8);
            float2 bb = *(const float2*)(sP + 128 + c + 8);
            float h00 = (D[2*kk][0]   - mu0) * inv0 * ga.x + ba.x;
            float h01 = (D[2*kk][1]   - mu0) * inv0 * ga.y + ba.y;
            float h10 = (D[2*kk][2]   - mu1) * inv1 * ga.x + ba.x;
            float h11 = (D[2*kk][3]   - mu1) * inv1 * ga.y + ba.y;
            float h08 = (D[2*kk+1][0] - mu0) * inv0 * gb.x + bb.x;
            float h09 = (D[2*kk+1][1] - mu0) * inv0 * gb.y + bb.y;
            float h18 = (D[2*kk+1][2] - mu1) * inv1 * gb.x + bb.x;
            float h19 = (D[2*kk+1][3] - mu1) * inv1 * gb.y + bb.y;
            split_pair(h00, h01, Ah[kk][0], Al[kk][0]);
            split_pair(h10, h11, Ah[kk][1], Al[kk][1]);
            split_pair(h08, h09, Ah[kk][2], Al[kk][2]);
            split_pair(h18, h19, Ah[kk][3], Al[kk][3]);
        }

        gemm16_2<false>(D, Ah, Al, sW + 2048, nullptr, lane);
        #pragma unroll
        for (int nn = 0; nn < 8; nn++) {
            const int pp = 16 * (nn >> 1) + 4 * m + 2 * (nn & 1);
            if (ok0) *(float2*)(g_q + (size_t)row0 * 64 + pp) = make_float2(D[nn][0], D[nn][1]);
            if (ok1) *(float2*)(g_q + (size_t)row1 * 64 + pp) = make_float2(D[nn][2], D[nn][3]);
        }
        gemm16_2<false>(D, Ah, Al, sW + 4096, nullptr, lane);
        #pragma unroll
        for (int nn = 0; nn < 8; nn++) {
            const int pp = 16 * (nn >> 1) + 4 * m + 2 * (nn & 1);
            if (ok0) *(float2*)(g_k + (size_t)row0 * 64 + pp) = make_float2(D[nn][0], D[nn][1]);
            if (ok1) *(float2*)(g_k + (size_t)row1 * 64 + pp) = make_float2(D[nn][2], D[nn][3]);
        }
        gemm16_2<false>(D, Ah, Al, sW + 6144, nullptr, lane);
        #pragma unroll
        for (int nn = 0; nn < 8; nn++) {
            const int vi = 8 * (nn >> 1) + 2 * m + (nn & 1);
            if (ok0) g_vh[(size_t)row0 * 32 + vi] = pack_f16x2(D[nn][0], D[nn][1]);
            if (ok1) g_vh[(size_t)row1 * 32 + vi] = pack_f16x2(D[nn][2], D[nn][3]);
        }

        float4* accz = (float4*)(g_acc + (size_t)base * 128);
        #pragma unroll
        for (int i = 0; i < 16; i++) {
            int idx = i * 32 + lane;
            if (base + (idx >> 5) < N)
                accz[idx] = make_float4(0.f, 0.f, 0.f, 0.f);
        }
    }
}

// ---------------------------------------------------------------------------
// Edge kernel: 16-edge mma tiles. GEMM1/GEMM3 use A-hi-only (1-mma) path,
// GEMM2 (attention logits) keeps the full hi/lo split (measured optimum).
// Packed int2 edges, float4 pos, fp16 v gathers, fp32 QK, index prefetch.
// ---------------------------------------------------------------------------
#define EDGE_SMEM (3 * 2048 * 4 + 64 * 16 + 3 * 64 * 4)   // 26368 B

__global__ void __launch_bounds__(128, 3) k_edge(
        int E,
        const float* __restrict__ pnW1, const float* __restrict__ pnb1,
        const float* __restrict__ pnb2, const float* __restrict__ anb1,
        const float* __restrict__ anb2) {
    extern __shared__ unsigned smu[];
    unsigned* sWL = smu;
    float4*  sW1  = (float4*)(smu + 6144);
    float*   sB   = (float*)(smu + 6144 + 256);   // 3 x 64 floats, paired layout

    {
        const uint4* src = (const uint4*)g_wfrag_edge;
        uint4* dst = (uint4*)sWL;
        for (int i = threadIdx.x; i < 1536; i += 128) dst[i] = src[i];
    }
    if (threadIdx.x < 64) {
        int c = threadIdx.x;
        sW1[c] = make_float4(pnW1[c], pnW1[64 + c], pnW1[128 + c], pnb1[c]);
        int pidx = bias_paired_idx(c);
        sB[pidx]        = pnb2[c];
        sB[64 + pidx]   = anb1[c];
        sB[128 + pidx]  = anb2[c];
    }
    __syncthreads();

    const int lane = threadIdx.x & 31, warp = threadIdx.x >> 5;
    const int r0 = lane >> 2, m = lane & 3;
    const int gw = blockIdx.x * 4 + warp;
    const int nw = gridDim.x * 4;
    const int ntiles = (E + 15) >> 4;

    unsigned Ah[4][4], Al[4][4];
    float D[8][4];
    float Dlt[8][4];
    float QK[8][4];

    int t = gw;
    int2 pe0 = make_int2(0, 0), pe1 = make_int2(0, 0);
    if (t < ntiles) {
        const int base = t << 4;
        pe0 = g_epack[min(base + r0, E - 1)];
        pe1 = g_epack[min(base + r0 + 8, E - 1)];
    }

    for (; t < ntiles; t += nw) {
        const int base = t << 4;
        const bool ok0 = base + r0 < E, ok1 = base + r0 + 8 < E;
        const int s0 = pe0.x, d0 = pe0.y, s1 = pe1.x, d1 = pe1.y;

        const int tn = t + nw;
        if (tn < ntiles) {
            const int nb = tn << 4;
            pe0 = g_epack[min(nb + r0, E - 1)];
            pe1 = g_epack[min(nb + r0 + 8, E - 1)];
        }

        // padded pos loads: one LDG.128 per endpoint
        float4 pD0 = g_pos4[d0], pS0 = g_pos4[s0];
        float4 pD1 = g_pos4[d1], pS1 = g_pos4[s1];
        const float p00 = pD0.x - pS0.x, p01 = pD0.y - pS0.y, p02 = pD0.z - pS0.z;
        const float p10 = pD1.x - pS1.x, p11 = pD1.y - pS1.y, p12 = pD1.z - pS1.z;

        // q/k fragment gathers: one float4 per (kk, row-stream), permuted layout
        #pragma unroll
        for (int kk = 0; kk < 4; kk++) {
            const int fp = kk * 16 + 4 * m;
            float4 qa = *(const float4*)(g_q + (size_t)d0 * 64 + fp);
            float4 ka = *(const float4*)(g_k + (size_t)s0 * 64 + fp);
            float4 qb = *(const float4*)(g_q + (size_t)d1 * 64 + fp);
            float4 kb = *(const float4*)(g_k + (size_t)s1 * 64 + fp);
            QK[2*kk][0]   = qa.x - ka.x; QK[2*kk][1]   = qa.y - ka.y;
            QK[2*kk+1][0] = qa.z - ka.z; QK[2*kk+1][1] = qa.w - ka.w;
            QK[2*kk][2]   = qb.x - kb.x; QK[2*kk][3]   = qb.y - kb.y;
            QK[2*kk+1][2] = qb.z - kb.z; QK[2*kk+1][3] = qb.w - kb.w;
        }

        // pos MLP layer 1 (3 -> 64), fp32, A-hi-only fragments
        #pragma unroll
        for (int kk = 0; kk < 4; kk++) {
            const int cb = kk * 16 + 2 * m;
            float4 wA = sW1[cb],     wB = sW1[cb + 1];
            float4 wC = sW1[cb + 8], wD = sW1[cb + 9];
            float h00 = fmaxf(fmaf(p02, wA.z, fmaf(p01, wA.y, fmaf(p00, wA.x, wA.w))), 0.f);
            float h01 = fmaxf(fmaf(p02, wB.z, fmaf(p01, wB.y, fmaf(p00, wB.x, wB.w))), 0.f);
            float h10 = fmaxf(fmaf(p12, wA.z, fmaf(p11, wA.y, fmaf(p10, wA.x, wA.w))), 0.f);
            float h11 = fmaxf(fmaf(p12, wB.z, fmaf(p11, wB.y, fmaf(p10, wB.x, wB.w))), 0.f);
            float h08 = fmaxf(fmaf(p02, wC.z, fmaf(p01, wC.y, fmaf(p00, wC.x, wC.w))), 0.f);
            float h09 = fmaxf(fmaf(p02, wD.z, fmaf(p01, wD.y, fmaf(p00, wD.x, wD.w))), 0.f);
            float h18 = fmaxf(fmaf(p12, wC.z, fmaf(p11, wC.y, fmaf(p10, wC.x, wC.w))), 0.f);
            float h19 = fmaxf(fmaf(p12, wD.z, fmaf(p11, wD.y, fmaf(p10, wD.x, wD.w))), 0.f);
            Ah[kk][0] = pack_f16x2(h00, h01);
            Ah[kk][1] = pack_f16x2(h10, h11);
            Ah[kk][2] = pack_f16x2(h08, h09);
            Ah[kk][3] = pack_f16x2(h18, h19);
        }

        // GEMM1 (A hi-only): delta = relu(H1 @ pnW2 + pnb2)
        gemm16_h<true>(D, Ah, sWL, sB, lane);
        #pragma unroll
        for (int nn = 0; nn < 8; nn++) {
            Dlt[nn][0] = fmaxf(D[nn][0], 0.f);
            Dlt[nn][1] = fmaxf(D[nn][1], 0.f);
            Dlt[nn][2] = fmaxf(D[nn][2], 0.f);
            Dlt[nn][3] = fmaxf(D[nn][3], 0.f);
        }

        // A2 = QK + delta  (full hi/lo split: logits are cancellation-sensitive)
        #pragma unroll
        for (int kk = 0; kk < 4; kk++) {
            split_pair(QK[2*kk][0]   + Dlt[2*kk][0],   QK[2*kk][1]   + Dlt[2*kk][1],   Ah[kk][0], Al[kk][0]);
            split_pair(QK[2*kk][2]   + Dlt[2*kk][2],   QK[2*kk][3]   + Dlt[2*kk][3],   Ah[kk][1], Al[kk][1]);
            split_pair(QK[2*kk+1][0] + Dlt[2*kk+1][0], QK[2*kk+1][1] + Dlt[2*kk+1][1], Ah[kk][2], Al[kk][2]);
            split_pair(QK[2*kk+1][2] + Dlt[2*kk+1][2], QK[2*kk+1][3] + Dlt[2*kk+1][3], Ah[kk][3], Al[kk][3]);
        }

        // GEMM2 (full): G = relu(A2 @ anW1 + anb1); pack G hi-only for GEMM3
        gemm16_2<true>(D, Ah, Al, sWL + 2048, sB + 64, lane);
        #pragma unroll
        for (int kk = 0; kk < 4; kk++) {
            Ah[kk][0] = pack_f16x2(fmaxf(D[2*kk][0], 0.f),   fmaxf(D[2*kk][1], 0.f));
            Ah[kk][1] = pack_f16x2(fmaxf(D[2*kk][2], 0.f),   fmaxf(D[2*kk][3], 0.f));
            Ah[kk][2] = pack_f16x2(fmaxf(D[2*kk+1][0], 0.f), fmaxf(D[2*kk+1][1], 0.f));
            Ah[kk][3] = pack_f16x2(fmaxf(D[2*kk+1][2], 0.f), fmaxf(D[2*kk+1][3], 0.f));
        }

        // v gathers (fp16 packed; reuse QK storage)
        #pragma unroll
        for (int j = 0; j < 4; j++) {
            const int vi = 8 * j + 2 * m;
            uint2 v0 = *(const uint2*)(g_vh + (size_t)s0 * 32 + vi);
            uint2 v1 = *(const uint2*)(g_vh + (size_t)s1 * 32 + vi);
            float2 a = unpack_f16x2(v0.x);
            float2 b = unpack_f16x2(v0.y);
            float2 c = unpack_f16x2(v1.x);
            float2 d2 = unpack_f16x2(v1.y);
            QK[2*j][0]   = a.x; QK[2*j][1]   = a.y;
            QK[2*j+1][0] = b.x; QK[2*j+1][1] = b.y;
            QK[2*j][2]   = c.x; QK[2*j][3]   = c.y;
            QK[2*j+1][2] = d2.x; QK[2*j+1][3] = d2.y;
        }

        // GEMM3 (A hi-only): alpha = G @ anW2 + anb2
        gemm16_h<true>(D, Ah, sWL + 4096, sB + 128, lane);

        // epilogue -> REDs at permuted acc positions
        #pragma unroll
        for (int nn = 0; nn < 8; nn++) {
            const int pp = 16 * (nn >> 1) + 4 * m + 2 * (nn & 1);
            float e00 = __expf(fmaxf(D[nn][0], 0.f));
            float e01 = __expf(fmaxf(D[nn][1], 0.f));
            float e10 = __expf(fmaxf(D[nn][2], 0.f));
            float e11 = __expf(fmaxf(D[nn][3], 0.f));
            if (ok0)
                red_add_v4(g_acc + (size_t)d0 * 128 + 2 * pp,
                           e00 * (QK[nn][0] + Dlt[nn][0]), e00,
                           e01 * (QK[nn][1] + Dlt[nn][1]), e01);
            if (ok1)
                red_add_v4(g_acc + (size_t)d1 * 128 + 2 * pp,
                           e10 * (QK[nn][2] + Dlt[nn][2]), e10,
                           e11 * (QK[nn][3] + Dlt[nn][3]), e11);
        }
    }
}

// ---------------------------------------------------------------------------
// Output kernel: reads permuted acc, fp16 2-mma GEMM (paired bias), natural store.
// ---------------------------------------------------------------------------
#define OUT_SMEM (2048 * 4 + 64 * 4)
__global__ void __launch_bounds__(256, 2) k_out(
        int N, const float* __restrict__ b_out, float* __restrict__ out) {
    extern __shared__ unsigned smu[];
    unsigned* sW = smu;
    float* sB = (float*)(smu + 2048);

    {
        const uint4* src = (const uint4*)g_wfrag_out;
        uint4* dst = (uint4*)sW;
        for (int i = threadIdx.x; i < 512; i += blockDim.x) dst[i] = src[i];
    }
    if (threadIdx.x < 64) sB[bias_paired_idx(threadIdx.x)] = b_out[threadIdx.x];
    __syncthreads();

    const int lane = threadIdx.x & 31, warp = threadIdx.x >> 5;
    const int r0 = lane >> 2, m = lane & 3;
    const int gw = blockIdx.x * (blockDim.x >> 5) + warp;
    const int nw = gridDim.x * (blockDim.x >> 5);
    const int ntiles = (N + 15) >> 4;

    unsigned Ah[4][4], Al[4][4];
    float D[8][4];

    for (int t = gw; t < ntiles; t += nw) {
        const int base = t << 4;
        const int row0 = base + r0, row1 = base + r0 + 8;
        const bool ok0 = row0 < N, ok1 = row1 < N;
        const int rr0 = ok0 ? row0 : N - 1;
        const int rr1 = ok1 ? row1 : N - 1;

        #pragma unroll
        for (int kk = 0; kk < 4; kk++) {
            const int fb = 32 * kk + 8 * m;
            float4 a0 = *(const float4*)(g_acc + (size_t)rr0 * 128 + fb);
            float4 a2 = *(const float4*)(g_acc + (size_t)rr0 * 128 + fb + 4);
            float4 a1 = *(const float4*)(g_acc + (size_t)rr1 * 128 + fb);
            float4 a3 = *(const float4*)(g_acc + (size_t)rr1 * 128 + fb + 4);
            split_pair(__fdividef(a0.x, a0.y + 1e-16f), __fdividef(a0.z, a0.w + 1e-16f),
                       Ah[kk][0], Al[kk][0]);
            split_pair(__fdividef(a1.x, a1.y + 1e-16f), __fdividef(a1.z, a1.w + 1e-16f),
                       Ah[kk][1], Al[kk][1]);
            split_pair(__fdividef(a2.x, a2.y + 1e-16f), __fdividef(a2.z, a2.w + 1e-16f),
                       Ah[kk][2], Al[kk][2]);
            split_pair(__fdividef(a3.x, a3.y + 1e-16f), __fdividef(a3.z, a3.w + 1e-16f),
                       Ah[kk][3], Al[kk][3]);
        }

        gemm16_2<true>(D, Ah, Al, sW, sB, lane);

        #pragma unroll
        for (int nn = 0; nn < 8; nn++) {
            const int c = nn * 8 + 2 * m;
            if (ok0) *(float2*)(out + (size_t)row0 * 64 + c) =
                make_float2(fmaxf(D[nn][0], 0.f), fmaxf(D[nn][1], 0.f));
            if (ok1) *(float2*)(out + (size_t)row1 * 64 + c) =
                make_float2(fmaxf(D[nn][2], 0.f), fmaxf(D[nn][3], 0.f));
        }
    }
}

// ---------------------------------------------------------------------------

extern "C" void kernel_launch(void* const* d_in, const int* in_sizes, int n_in,
                              void* d_out, int out_size) {
    const float* x     = (const float*)d_in[0];
    const float* pos   = (const float*)d_in[1];
    const int*   ei    = (const int*)d_in[2];
    const float* W_in  = (const float*)d_in[3];
    const float* b_in  = (const float*)d_in[4];
    const float* ln_g  = (const float*)d_in[5];
    const float* ln_b  = (const float*)d_in[6];
    const float* W_lin = (const float*)d_in[7];
    const float* W_src = (const float*)d_in[8];
    const float* W_dst = (const float*)d_in[9];
    const float* pnW1  = (const float*)d_in[10];
    const float* pnb1  = (const float*)d_in[11];
    const float* pnW2  = (const float*)d_in[12];
    const float* pnb2  = (const float*)d_in[13];
    const float* anW1  = (const float*)d_in[14];
    const float* anb1  = (const float*)d_in[15];
    const float* anW2  = (const float*)d_in[16];
    const float* anb2  = (const float*)d_in[17];
    const float* W_out = (const float*)d_in[18];
    const float* b_out = (const float*)d_in[19];

    const int N = in_sizes[0] / 64;
    const int E = in_sizes[2] / 2;

    cudaFuncSetAttribute(k_node, cudaFuncAttributeMaxDynamicSharedMemorySize, NODE_SMEM);
    cudaFuncSetAttribute(k_edge, cudaFuncAttributeMaxDynamicSharedMemorySize, EDGE_SMEM);
    cudaFuncSetAttribute(k_out,  cudaFuncAttributeMaxDynamicSharedMemorySize, OUT_SMEM);

    k_prep<<<128, 256>>>(W_in, W_dst, W_src, W_lin, pnW2, anW1, anW2, W_out,
                         pos, ei, N, E);
    k_node<<<296, 256, NODE_SMEM>>>(N, x, b_in, ln_g, ln_b);
    k_edge<<<444, 128, EDGE_SMEM>>>(E, pnW1, pnb1, pnb2, anb1, anb2);
    k_out<<<296, 256, OUT_SMEM>>>(N, b_out, (float*)d_out);
}